// round 12
// baseline (speedup 1.0000x reference)
#include <cuda_runtime.h>
#include <math.h>
#include <stdint.h>

#define NROWS 100000
#define DIMS  1443
#define NB    148
#define NT    768
#define NWARP 24
#define TOTW  (NB*NWARP)        // 3552
#define GSTRIDE (NB*NT)
#define WPP   (37*NWARP)        // 888 warps per alignment phase
#define NQUAD 6250              // 25000 rows-per-phase / 4 rows-per-warp-iter
#define JPP   25000
#define SCAP  1024
#define PDEPTH 4
#define STAGEF4 (4*32)          // 4 rows x 32 float4 per stage
#define WPACK_BYTES (3*360*16)                    // 17280
#define STAGE_BYTES (NWARP*PDEPTH*STAGEF4*16)     // 196608
#define DSMEM (WPACK_BYTES + STAGE_BYTES)         // 213888

// ---------------- device scratch (allocation-free) ----------------
__device__ unsigned g_bar = 0;
__device__ float    g_y1[NROWS], g_y2[NROWS], g_y3[NROWS];
__device__ float    g_prod[NROWS];
__device__ float    g_coef[NROWS];
__device__ unsigned g_key[NROWS];
__device__ unsigned g_hist[3][65536];     // zeroed in C4 of its round (replay invariant)
__device__ unsigned g_hist8[3][256];      // coarse (key>>24), same lifecycle
__device__ unsigned g_candk[NROWS];
__device__ int      g_candr[NROWS];
__device__ int      g_ncand3[3];
__device__ float    g_fpart[TOTW][DIMS];
__device__ float    g_epart[16][DIMS];

__device__ __forceinline__ unsigned f2key(float f) {
    unsigned u = __float_as_uint(f);
    return (u & 0x80000000u) ? ~u : (u | 0x80000000u);   // never 0 for finite f
}
__device__ __forceinline__ uint32_t s2u(const void* p) {
    uint32_t a;
    asm("{ .reg .u64 t; cvta.to.shared.u64 t, %1; cvt.u32.u64 %0, t; }"
        : "=r"(a) : "l"(p));
    return a;
}
__device__ __forceinline__ void cpa16(uint32_t dst, const void* src) {
    asm volatile("cp.async.cg.shared.global [%0], [%1], 16;"
                 :: "r"(dst), "l"(src) : "memory");
}
__device__ __forceinline__ void cpa_commit() {
    asm volatile("cp.async.commit_group;" ::: "memory");
}
__device__ __forceinline__ void cpa_waitP() {
    asm volatile("cp.async.wait_group %0;" :: "n"(PDEPTH - 1) : "memory");
}

// grid barrier: bar.sync gives intra-block HB; tid0 fence+atomic publishes.
__device__ __forceinline__ void gbar(unsigned ph) {
    __syncthreads();
    if (threadIdx.x == 0) {
        __threadfence();
        atomicAdd(&g_bar, 1u);
        const unsigned tgt = ph * NB;
        while (atomicAdd(&g_bar, 0u) < tgt) __nanosleep(128);
        __threadfence();
    }
    __syncthreads();
}

// per-row round update; returns new key (0 if dropped / r==2)
__device__ __forceinline__ unsigned upd(int r, int i, bool sel,
                                        float i1, float i2, float i3) {
    if (r == 0) {
        if (sel) {
            float s = tanhf(__ldcg(&g_y1[i]) * i1);
            g_prod[i] = s;
            unsigned nk = f2key(s * __ldcg(&g_y2[i]));
            g_key[i] = nk;
            return nk;
        }
        g_key[i] = 0u; return 0u;
    } else if (r == 1) {
        if (sel) {
            float p = __ldcg(&g_prod[i]);
            float s = tanhf(p * __ldcg(&g_y2[i]) * i2);
            p *= s;
            g_prod[i] = p;
            unsigned nk = f2key(p * __ldcg(&g_y3[i]));
            g_key[i] = nk;
            return nk;
        }
        g_key[i] = 0u; return 0u;
    } else {
        float cf = 0.f;
        if (sel) {
            float p = __ldcg(&g_prod[i]);
            float s = tanhf(p * __ldcg(&g_y3[i]) * i3);
            cf = p * s * (1.0f / 12500.0f);
        }
        g_coef[i] = cf;
        return 0u;
    }
}

extern __shared__ float4 dsm4[];   // [w-pack 1080 f4][stages 24*4*128 f4]

__global__ void __launch_bounds__(NT, 1) k_persist(
    const float* __restrict__ x,
    const float* __restrict__ w1, const float* __restrict__ w2,
    const float* __restrict__ w3, float* __restrict__ out)
{
    const int tid  = threadIdx.x, bid = blockIdx.x;
    const int lane = tid & 31,    wid = tid >> 5;
    const int gw   = bid * NWARP + wid;
    const int gtid = bid * NT + tid;
    const int p    = bid & 3;                  // alignment phase of this block
    const int wp   = (bid >> 2) * NWARP + wid; // warp id within phase [0,888)

    float4* s_wp = dsm4;                       // [3][360]
    float4* s_st = dsm4 + 3 * 360;             // [24][PDEPTH][4][32]

    __shared__ float    s_n[3][NWARP];
    __shared__ float    s_inv[3];
    __shared__ unsigned s_scan[256];
    __shared__ unsigned s_ck[SCAP];
    __shared__ int      s_cr[SCAP];
    __shared__ unsigned s_Bsel;
    __shared__ int      s_needB;
    __shared__ int      s_cb, s_nr;

    // ---- w norms (block-local, redundant across blocks) ----
    {
        float a0 = 0.f, a1 = 0.f, a2 = 0.f;
        for (int i = tid; i < DIMS; i += NT) {
            float v1 = __ldg(w1 + i), v2 = __ldg(w2 + i), v3 = __ldg(w3 + i);
            a0 += v1 * v1; a1 += v2 * v2; a2 += v3 * v3;
        }
#pragma unroll
        for (int off = 16; off > 0; off >>= 1) {
            a0 += __shfl_down_sync(0xffffffffu, a0, off);
            a1 += __shfl_down_sync(0xffffffffu, a1, off);
            a2 += __shfl_down_sync(0xffffffffu, a2, off);
        }
        if (lane == 0) { s_n[0][wid] = a0; s_n[1][wid] = a1; s_n[2][wid] = a2; }
    }
    // ---- fill phase-local w-pack; zero counters ----
    for (int idx = tid; idx < 3 * 360; idx += NT) {
        int v = idx / 360, m = idx % 360;
        const float* w = (v == 0) ? w1 : ((v == 1) ? w2 : w3);
        int col = p + 4 * m;
        s_wp[idx] = make_float4(__ldg(w + col), __ldg(w + col + 1),
                                __ldg(w + col + 2), __ldg(w + col + 3));
    }
    if (bid == 0 && tid < 3) g_ncand3[tid] = 0;
    __syncthreads();
    if (tid < 3) {
        float s = 0.f;
        for (int w = 0; w < NWARP; w++) s += s_n[tid][w];
        s_inv[tid] = 1.0f / sqrtf(s);
    }
    __syncthreads();
    const float i1 = s_inv[0], i2 = s_inv[1], i3 = s_inv[2];

    // ---------------- phase B: GEMV, cp.async depth-4 per-warp pipeline ----------------
    {
        const float4* wpa = s_wp;
        const float4* wpb = s_wp + 360;
        const float4* wpc = s_wp + 720;
        const int e = lane - 8;
        const bool haveE = (e >= 0 && e < 3);
        int ecol = 0; float we1 = 0.f, we2 = 0.f, we3 = 0.f;
        if (haveE) {
            ecol = (e < p) ? e : p + 1440 + (e - p);
            we1 = __ldg(w1 + ecol); we2 = __ldg(w2 + ecol); we3 = __ldg(w3 + ecol);
        }
        const int  m11 = (lane < 8) ? (352 + lane) : 359;   // safe in-row dup
        const bool l8  = (lane < 8);
        const char* xb = (const char*)(x + p);              // +row*5772 bytes
        const uint32_t stBase = s2u(s_st) +
            (uint32_t)(wid * PDEPTH * STAGEF4 + lane) * 16u;
        int gP = wp, kP = 0;
        auto issue = [&](int slot) {
            if (gP < NQUAD) {
                const int m = (kP < 11) ? (lane + 32 * kP) : m11;
                const char* src = xb + (size_t)(p + 16 * gP) * (DIMS * 4) + 16 * m;
                uint32_t dst = stBase + (uint32_t)(slot * STAGEF4) * 16u;
                cpa16(dst,             src);
                cpa16(dst + 32u * 16u, src + 4 * (DIMS * 4));
                cpa16(dst + 64u * 16u, src + 8 * (DIMS * 4));
                cpa16(dst + 96u * 16u, src + 12 * (DIMS * 4));
            }
            cpa_commit();
            if (++kP == 12) { kP = 0; gP += WPP; }
        };
#pragma unroll
        for (int d = 0; d < PDEPTH; d++) issue(d);

        int slot = 0;
        const float4* sl = s_st + wid * PDEPTH * STAGEF4 + lane;
        for (int gC = wp; gC < NQUAD; gC += WPP) {
            const int rbase = p + 16 * gC;
            float acc[12];
#pragma unroll
            for (int v = 0; v < 12; v++) acc[v] = 0.f;
            float xe0 = 0.f, xe1 = 0.f, xe2 = 0.f, xe3 = 0.f;
            if (haveE) {
                xe0 = __ldcg(x + (size_t)(rbase     ) * DIMS + ecol);
                xe1 = __ldcg(x + (size_t)(rbase +  4) * DIMS + ecol);
                xe2 = __ldcg(x + (size_t)(rbase +  8) * DIMS + ecol);
                xe3 = __ldcg(x + (size_t)(rbase + 12) * DIMS + ecol);
            }
#pragma unroll 4
            for (int k = 0; k < 12; k++) {
                cpa_waitP();                      // oldest stage (slot) ready
                const float4* sb = sl + slot * STAGEF4;
                float4 v0 = sb[0], v1 = sb[32], v2 = sb[64], v3 = sb[96];
                const int m = (k < 11) ? (lane + 32 * k) : m11;
                float4 wa = wpa[m], wb = wpb[m], wc = wpc[m];
                if (k == 11 && !l8) {
                    wa = make_float4(0.f, 0.f, 0.f, 0.f); wb = wa; wc = wa;
                }
                acc[0]  += v0.x*wa.x + v0.y*wa.y + v0.z*wa.z + v0.w*wa.w;
                acc[1]  += v0.x*wb.x + v0.y*wb.y + v0.z*wb.z + v0.w*wb.w;
                acc[2]  += v0.x*wc.x + v0.y*wc.y + v0.z*wc.z + v0.w*wc.w;
                acc[3]  += v1.x*wa.x + v1.y*wa.y + v1.z*wa.z + v1.w*wa.w;
                acc[4]  += v1.x*wb.x + v1.y*wb.y + v1.z*wb.z + v1.w*wb.w;
                acc[5]  += v1.x*wc.x + v1.y*wc.y + v1.z*wc.z + v1.w*wc.w;
                acc[6]  += v2.x*wa.x + v2.y*wa.y + v2.z*wa.z + v2.w*wa.w;
                acc[7]  += v2.x*wb.x + v2.y*wb.y + v2.z*wb.z + v2.w*wb.w;
                acc[8]  += v2.x*wc.x + v2.y*wc.y + v2.z*wc.z + v2.w*wc.w;
                acc[9]  += v3.x*wa.x + v3.y*wa.y + v3.z*wa.z + v3.w*wa.w;
                acc[10] += v3.x*wb.x + v3.y*wb.y + v3.z*wb.z + v3.w*wb.w;
                acc[11] += v3.x*wc.x + v3.y*wc.y + v3.z*wc.z + v3.w*wc.w;
                issue(slot);                      // refill this slot (newest group)
                slot = (slot + 1) & (PDEPTH - 1);
            }
            if (haveE) {
                acc[0] += xe0 * we1; acc[1] += xe0 * we2; acc[2]  += xe0 * we3;
                acc[3] += xe1 * we1; acc[4] += xe1 * we2; acc[5]  += xe1 * we3;
                acc[6] += xe2 * we1; acc[7] += xe2 * we2; acc[8]  += xe2 * we3;
                acc[9] += xe3 * we1; acc[10]+= xe3 * we2; acc[11] += xe3 * we3;
            }
#pragma unroll
            for (int off = 16; off > 0; off >>= 1)
#pragma unroll
                for (int v = 0; v < 12; v++)
                    acc[v] += __shfl_down_sync(0xffffffffu, acc[v], off);
            if (lane == 0) {
#pragma unroll
                for (int u = 0; u < 4; u++) {
                    int r = rbase + 4 * u;
                    g_y1[r] = acc[u * 3 + 0];
                    g_y2[r] = acc[u * 3 + 1];
                    g_y3[r] = acc[u * 3 + 2];
                    unsigned key = f2key(acc[u * 3 + 0]);
                    g_key[r] = key;
                    atomicAdd(&g_hist[0][key >> 16], 1u);   // fused round-0 hist
                    atomicAdd(&g_hist8[0][key >> 24], 1u);
                }
            }
        }
        asm volatile("cp.async.wait_group 0;" ::: "memory");  // drain tail groups
    }
    unsigned ph = 0;
    gbar(++ph);

    // ---------------- selection rounds (2 barriers each) ----------------
    for (int r = 0; r < 3; r++) {
        const int need = (r == 0) ? 50000 : ((r == 1) ? 25000 : 12500);
        unsigned* hist = g_hist[r];

        // C2: two-level scan in EVERY block (512 bin reads total)
        {
            unsigned own = 0;
            if (tid < 256) {
                own = __ldcg(&g_hist8[r][255 - tid]);
                s_scan[tid] = own;
            }
            __syncthreads();
#pragma unroll
            for (int off = 1; off < 256; off <<= 1) {
                unsigned v = (tid >= off && tid < 256) ? s_scan[tid - off] : 0u;
                __syncthreads();
                if (tid < 256) s_scan[tid] += v;
                __syncthreads();
            }
            if (tid < 256) {
                unsigned incl = s_scan[tid], excl = incl - own;
                if ((int)excl < need && need <= (int)incl) {
                    s_cb = 255 - tid;
                    s_nr = need - (int)excl;
                }
            }
            __syncthreads();
            const int cb = s_cb, nr = s_nr;
            unsigned own2 = 0;
            if (tid < 256) {
                own2 = __ldcg(&hist[cb * 256 + 255 - tid]);
                s_scan[tid] = own2;
            }
            __syncthreads();
#pragma unroll
            for (int off = 1; off < 256; off <<= 1) {
                unsigned v = (tid >= off && tid < 256) ? s_scan[tid - off] : 0u;
                __syncthreads();
                if (tid < 256) s_scan[tid] += v;
                __syncthreads();
            }
            if (tid < 256) {
                unsigned incl = s_scan[tid], excl = incl - own2;
                if ((int)excl < nr && nr <= (int)incl) {
                    s_Bsel = (unsigned)(cb * 256 + 255 - tid);
                    s_needB = nr - (int)excl;
                }
            }
            __syncthreads();
        }

        // C3: classify + next-round hists + append boundary candidates
        {
            const unsigned Bv = s_Bsel;
            for (int i = gtid; i < NROWS; i += GSTRIDE) {
                unsigned key = __ldcg(&g_key[i]);
                if (key) {
                    unsigned b = key >> 16;
                    if (b > Bv) {
                        unsigned nk = upd(r, i, true, i1, i2, i3);
                        if (r < 2) {
                            atomicAdd(&g_hist[r + 1][nk >> 16], 1u);
                            atomicAdd(&g_hist8[r + 1][nk >> 24], 1u);
                        }
                    } else if (b == Bv) {
                        int ci = atomicAdd(&g_ncand3[r], 1);
                        g_candk[ci] = key; g_candr[ci] = i;
                    } else {
                        upd(r, i, false, i1, i2, i3);
                    }
                } else {
                    upd(r, i, false, i1, i2, i3);   // writes coef=0 when r==2
                }
            }
        }
        gbar(++ph);

        // C4 (all blocks): rank boundary candidates, strided ownership;
        //                  also re-zero hist[r]/hist8[r] (replay invariant)
        {
            for (int i = gtid; i < 65536; i += GSTRIDE) hist[i] = 0u;
            if (bid == 0 && tid < 256) g_hist8[r][tid] = 0u;
            int m  = __ldcg(&g_ncand3[r]);
            int nB = s_needB;
            int mc = (m < SCAP) ? m : SCAP;
            for (int j = tid; j < mc; j += NT) {
                s_ck[j] = __ldcg(&g_candk[j]);
                s_cr[j] = __ldcg(&g_candr[j]);
            }
            __syncthreads();
            for (int ci = gtid; ci < m; ci += GSTRIDE) {
                unsigned mk = (ci < mc) ? s_ck[ci] : __ldcg(&g_candk[ci]);
                int      mr = (ci < mc) ? s_cr[ci] : __ldcg(&g_candr[ci]);
                int cnt = 0;
                for (int j = 0; j < mc; j++) {
                    unsigned kj = s_ck[j]; int rj = s_cr[j];
                    cnt += (kj > mk || (kj == mk && rj < mr)) ? 1 : 0;
                }
                for (int j = mc; j < m; j++) {
                    unsigned kj = __ldcg(&g_candk[j]); int rj = __ldcg(&g_candr[j]);
                    cnt += (kj > mk || (kj == mk && rj < mr)) ? 1 : 0;
                }
                bool sel = (cnt < nB);
                unsigned nk = upd(r, mr, sel, i1, i2, i3);
                if (r < 2 && sel) {
                    atomicAdd(&g_hist[r + 1][nk >> 16], 1u);
                    atomicAdd(&g_hist8[r + 1][nk >> 24], 1u);
                }
            }
        }
        gbar(++ph);
    }

    // ---------------- phase D: weighted gather, single pass ----------------
    {
        const int e = lane - 8;
        const bool haveE = (e >= 0 && e < 3);
        const int ecol = haveE ? ((e < p) ? e : p + 1440 + (e - p)) : 0;
        const int m11 = 352 + lane;
        const bool l8 = (lane < 8);
        float* fp = &g_fpart[gw][0];
        float4 acc[12];
#pragma unroll
        for (int kk = 0; kk < 12; kk++) acc[kk] = make_float4(0.f, 0.f, 0.f, 0.f);
        float accE = 0.f;
        for (int jj = wp; jj < JPP; jj += WPP) {
            int row = p + 4 * jj;
            float c = __ldcg(&g_coef[row]);
            if (c == 0.0f) continue;
            const float4* px = (const float4*)(x + (size_t)row * DIMS + p);
#pragma unroll
            for (int k = 0; k < 11; k++) {
                float4 v = __ldg(px + lane + 32 * k);
                acc[k].x += c * v.x; acc[k].y += c * v.y;
                acc[k].z += c * v.z; acc[k].w += c * v.w;
            }
            if (l8) {
                float4 v = __ldg(px + m11);
                acc[11].x += c * v.x; acc[11].y += c * v.y;
                acc[11].z += c * v.z; acc[11].w += c * v.w;
            }
            if (haveE) accE += c * __ldg(x + (size_t)row * DIMS + ecol);
        }
#pragma unroll
        for (int k = 0; k < 12; k++) {
            if (k < 11 || l8) {
                int m = (k < 11) ? (lane + 32 * k) : m11;
                int cb = p + 4 * m;
                fp[cb] = acc[k].x; fp[cb + 1] = acc[k].y;
                fp[cb + 2] = acc[k].z; fp[cb + 3] = acc[k].w;
            }
        }
        if (haveE) fp[ecol] = accE;
    }
    gbar(++ph);

    // ---------------- E1: reduce 3552 partials -> 16 ----------------
    if (gw < 736) {
        int q = gw & 15, cg = gw >> 4;
        int col = cg * 32 + lane;
        if (col < DIMS) {
            float s = 0.f;
            int j0 = q * (TOTW / 16);
#pragma unroll 8
            for (int j = j0; j < j0 + (TOTW / 16); j++) s += __ldcg(&g_fpart[j][col]);
            g_epart[q][col] = s;
        }
    }
    gbar(++ph);

    // ---------------- E2: 16 -> out ----------------
    if (gw < 46) {
        int col = gw * 32 + lane;
        if (col < DIMS) {
            float s = 0.f;
#pragma unroll
            for (int q = 0; q < 16; q++) s += __ldcg(&g_epart[q][col]);
            out[col] = s;
        }
    }

    // ---- final arrive-only barrier; block 0 resets counter for next replay ----
    __syncthreads();
    if (tid == 0) {
        __threadfence();
        const unsigned tgt = (ph + 1) * NB;
        atomicAdd(&g_bar, 1u);
        if (bid == 0) {
            while (atomicAdd(&g_bar, 0u) < tgt) __nanosleep(128);
            atomicExch(&g_bar, 0u);
            __threadfence();
        }
    }
}

// ---------------- launch ----------------
extern "C" void kernel_launch(void* const* d_in, const int* in_sizes, int n_in,
                              void* d_out, int out_size) {
    const float* x  = (const float*)d_in[0];
    // d_in[1] edge_index, d_in[2] edge_attr: dead inputs
    const float* w1 = (const float*)d_in[3];
    const float* w2 = (const float*)d_in[4];
    const float* w3 = (const float*)d_in[5];
    float* out = (float*)d_out;

    cudaFuncSetAttribute(k_persist, cudaFuncAttributeMaxDynamicSharedMemorySize,
                         DSMEM);
    k_persist<<<NB, NT, DSMEM>>>(x, w1, w2, w3, out);
}

// round 13
// speedup vs baseline: 1.1256x; 1.1256x over previous
#include <cuda_runtime.h>
#include <math.h>
#include <stdint.h>

#define NROWS 100000
#define DIMS  1443
#define NB    148
#define NT    512
#define NWARP 16
#define TOTW  (NB*NWARP)        // 2368
#define GSTRIDE (NB*NT)
#define WPP   (37*NWARP)        // 592 warps per alignment phase
#define JROWS 25000             // rows per phase: row = p + 4*jj, jj in [0,25000)
#define JPP   25000
#define SCAP  1024
#define RSTAGE 2
#define ROWB  5760              // 1440 floats (16B-aligned slice of a row)
#define WPACK_BYTES (3*360*16)              // 17280
#define ROWS_BYTES (NWARP*RSTAGE*ROWB)      // 184320
#define DSMEM (WPACK_BYTES + ROWS_BYTES)    // 201600

// ---------------- device scratch (allocation-free) ----------------
__device__ unsigned g_bar = 0;
__device__ float    g_y1[NROWS], g_y2[NROWS], g_y3[NROWS];
__device__ float    g_prod[NROWS];
__device__ float    g_coef[NROWS];
__device__ unsigned g_key[NROWS];
__device__ unsigned g_hist[3][65536];     // zeroed in C4 of its round (replay invariant)
__device__ unsigned g_hist8[3][256];      // coarse (key>>24), same lifecycle
__device__ unsigned g_candk[NROWS];
__device__ int      g_candr[NROWS];
__device__ int      g_ncand3[3];
__device__ float    g_fpart[TOTW][DIMS];
__device__ float    g_epart[16][DIMS];

__device__ __forceinline__ unsigned f2key(float f) {
    unsigned u = __float_as_uint(f);
    return (u & 0x80000000u) ? ~u : (u | 0x80000000u);   // never 0 for finite f
}
__device__ __forceinline__ uint32_t s2u(const void* p) {
    uint32_t a;
    asm("{ .reg .u64 t; cvta.to.shared.u64 t, %1; cvt.u32.u64 %0, t; }"
        : "=r"(a) : "l"(p));
    return a;
}
__device__ __forceinline__ void mb_init(uint32_t m, uint32_t c) {
    asm volatile("mbarrier.init.shared.b64 [%0], %1;" :: "r"(m), "r"(c) : "memory");
}
__device__ __forceinline__ void mb_extx(uint32_t m, uint32_t b) {
    asm volatile("mbarrier.arrive.expect_tx.shared.b64 _, [%0], %1;"
                 :: "r"(m), "r"(b) : "memory");
}
__device__ __forceinline__ void bulk_g2s(uint32_t dst, const void* src,
                                         uint32_t bytes, uint32_t m) {
    asm volatile("cp.async.bulk.shared::cta.global.mbarrier::complete_tx::bytes "
                 "[%0], [%1], %2, [%3];"
                 :: "r"(dst), "l"(src), "r"(bytes), "r"(m) : "memory");
}
__device__ __forceinline__ void mb_wait(uint32_t m, uint32_t par) {
    uint32_t done;
    asm volatile(
        "{ .reg .pred p; mbarrier.try_wait.parity.acquire.cta.shared::cta.b64 "
        "p, [%1], %2; selp.b32 %0,1,0,p; }"
        : "=r"(done) : "r"(m), "r"(par) : "memory");
    while (!done) {
        asm volatile(
            "{ .reg .pred p; mbarrier.try_wait.parity.acquire.cta.shared::cta.b64 "
            "p, [%1], %2, 0x989680; selp.b32 %0,1,0,p; }"
            : "=r"(done) : "r"(m), "r"(par) : "memory");
    }
}
__device__ __forceinline__ void fence_async() {
    asm volatile("fence.proxy.async.shared::cta;" ::: "memory");
}

// grid barrier: bar.sync gives intra-block HB; tid0 fence+atomic publishes.
__device__ __forceinline__ void gbar(unsigned ph) {
    __syncthreads();
    if (threadIdx.x == 0) {
        __threadfence();
        atomicAdd(&g_bar, 1u);
        const unsigned tgt = ph * NB;
        while (atomicAdd(&g_bar, 0u) < tgt) __nanosleep(128);
        __threadfence();
    }
    __syncthreads();
}

// per-row round update; returns new key (0 if dropped / r==2)
__device__ __forceinline__ unsigned upd(int r, int i, bool sel,
                                        float i1, float i2, float i3) {
    if (r == 0) {
        if (sel) {
            float s = tanhf(__ldcg(&g_y1[i]) * i1);
            g_prod[i] = s;
            unsigned nk = f2key(s * __ldcg(&g_y2[i]));
            g_key[i] = nk;
            return nk;
        }
        g_key[i] = 0u; return 0u;
    } else if (r == 1) {
        if (sel) {
            float p = __ldcg(&g_prod[i]);
            float s = tanhf(p * __ldcg(&g_y2[i]) * i2);
            p *= s;
            g_prod[i] = p;
            unsigned nk = f2key(p * __ldcg(&g_y3[i]));
            g_key[i] = nk;
            return nk;
        }
        g_key[i] = 0u; return 0u;
    } else {
        float cf = 0.f;
        if (sel) {
            float p = __ldcg(&g_prod[i]);
            float s = tanhf(p * __ldcg(&g_y3[i]) * i3);
            cf = p * s * (1.0f / 12500.0f);
        }
        g_coef[i] = cf;
        return 0u;
    }
}

extern __shared__ float4 dsm4[];   // [w-pack 1080 f4][row buffers 16*2*360 f4]

__global__ void __launch_bounds__(NT, 1) k_persist(
    const float* __restrict__ x,
    const float* __restrict__ w1, const float* __restrict__ w2,
    const float* __restrict__ w3, float* __restrict__ out)
{
    const int tid  = threadIdx.x, bid = blockIdx.x;
    const int lane = tid & 31,    wid = tid >> 5;
    const int gw   = bid * NWARP + wid;
    const int gtid = bid * NT + tid;
    const int p    = bid & 3;                  // alignment phase of this block
    const int wp   = (bid >> 2) * NWARP + wid; // warp id within phase [0,592)

    float4* s_wp = dsm4;                       // [3][360]
    float4* s_rw = dsm4 + 3 * 360;             // [16][RSTAGE][360]

    __shared__ float    s_n[3][NWARP];
    __shared__ float    s_inv[3];
    __shared__ unsigned s_scan[256];
    __shared__ unsigned s_ck[SCAP];
    __shared__ int      s_cr[SCAP];
    __shared__ unsigned s_Bsel;
    __shared__ int      s_needB;
    __shared__ int      s_cb, s_nr;
    __shared__ __align__(8) uint64_t s_mb[NWARP][RSTAGE];

    // ---- w norms (block-local, redundant across blocks) ----
    {
        float a0 = 0.f, a1 = 0.f, a2 = 0.f;
        for (int i = tid; i < DIMS; i += NT) {
            float v1 = __ldg(w1 + i), v2 = __ldg(w2 + i), v3 = __ldg(w3 + i);
            a0 += v1 * v1; a1 += v2 * v2; a2 += v3 * v3;
        }
#pragma unroll
        for (int off = 16; off > 0; off >>= 1) {
            a0 += __shfl_down_sync(0xffffffffu, a0, off);
            a1 += __shfl_down_sync(0xffffffffu, a1, off);
            a2 += __shfl_down_sync(0xffffffffu, a2, off);
        }
        if (lane == 0) { s_n[0][wid] = a0; s_n[1][wid] = a1; s_n[2][wid] = a2; }
    }
    // ---- fill phase-local w-pack; init mbarriers; zero counters ----
    for (int idx = tid; idx < 3 * 360; idx += NT) {
        int v = idx / 360, m = idx % 360;
        const float* w = (v == 0) ? w1 : ((v == 1) ? w2 : w3);
        int col = p + 4 * m;
        s_wp[idx] = make_float4(__ldg(w + col), __ldg(w + col + 1),
                                __ldg(w + col + 2), __ldg(w + col + 3));
    }
    if (tid < NWARP * RSTAGE) {
        mb_init(s2u(&s_mb[tid >> 1][tid & 1]), 1);
        fence_async();
    }
    if (bid == 0 && tid < 3) g_ncand3[tid] = 0;
    __syncthreads();
    if (tid < 3) {
        float s = 0.f;
        for (int w = 0; w < NWARP; w++) s += s_n[tid][w];
        s_inv[tid] = 1.0f / sqrtf(s);
    }
    __syncthreads();
    const float i1 = s_inv[0], i2 = s_inv[1], i3 = s_inv[2];

    // ---------------- phase B: GEMV, per-warp bulk-copy ring (TMA path) ----------------
    {
        const float4* wpa = s_wp;
        const float4* wpb = s_wp + 360;
        const float4* wpc = s_wp + 720;
        const int e = lane - 8;
        const bool haveE = (e >= 0 && e < 3);
        int ecol = 0; float we1 = 0.f, we2 = 0.f, we3 = 0.f;
        if (haveE) {
            ecol = (e < p) ? e : p + 1440 + (e - p);
            we1 = __ldg(w1 + ecol); we2 = __ldg(w2 + ecol); we3 = __ldg(w3 + ecol);
        }
        const uint32_t rwBase = s2u(s_rw);
        const uint32_t mbA[2] = { s2u(&s_mb[wid][0]), s2u(&s_mb[wid][1]) };

        auto issueRow = [&](int jj, int slot) {
            if (jj < JROWS && lane == 0) {
                int row = p + 4 * jj;
                const float* src = x + (size_t)row * DIMS + p;   // 16B aligned
                uint32_t dst = rwBase + (uint32_t)(wid * RSTAGE + slot) * ROWB;
                mb_extx(mbA[slot], ROWB);
                bulk_g2s(dst, src, ROWB, mbA[slot]);
            }
        };
        issueRow(wp, 0);
        issueRow(wp + WPP, 1);

        int phs0 = 0, phs1 = 0, t = 0;
        for (int jj = wp; jj < JROWS; jj += WPP, ++t) {
            const int slot = t & 1;
            const int row = p + 4 * jj;
            float xe = haveE ? __ldcg(x + (size_t)row * DIMS + ecol) : 0.f;
            if (slot == 0) { mb_wait(mbA[0], phs0); phs0 ^= 1; }
            else           { mb_wait(mbA[1], phs1); phs1 ^= 1; }
            const float4* rb = s_rw + (wid * RSTAGE + slot) * 360;
            float a0 = 0.f, a1 = 0.f, a2 = 0.f;
#pragma unroll
            for (int k = 0; k < 11; k++) {
                int m = lane + 32 * k;
                float4 v = rb[m];
                float4 wa = wpa[m], wbv = wpb[m], wc = wpc[m];
                a0 += v.x*wa.x  + v.y*wa.y  + v.z*wa.z  + v.w*wa.w;
                a1 += v.x*wbv.x + v.y*wbv.y + v.z*wbv.z + v.w*wbv.w;
                a2 += v.x*wc.x  + v.y*wc.y  + v.z*wc.z  + v.w*wc.w;
            }
            if (lane < 8) {
                int m = 352 + lane;
                float4 v = rb[m];
                float4 wa = wpa[m], wbv = wpb[m], wc = wpc[m];
                a0 += v.x*wa.x  + v.y*wa.y  + v.z*wa.z  + v.w*wa.w;
                a1 += v.x*wbv.x + v.y*wbv.y + v.z*wbv.z + v.w*wbv.w;
                a2 += v.x*wc.x  + v.y*wc.y  + v.z*wc.z  + v.w*wc.w;
            }
            if (haveE) { a0 += xe * we1; a1 += xe * we2; a2 += xe * we3; }
            fence_async();                // order this lane's smem reads before async reuse
            __syncwarp();                 // all lanes' fences precede lane0's re-issue
            issueRow(jj + 2 * WPP, slot); // refill slot
#pragma unroll
            for (int off = 16; off > 0; off >>= 1) {
                a0 += __shfl_down_sync(0xffffffffu, a0, off);
                a1 += __shfl_down_sync(0xffffffffu, a1, off);
                a2 += __shfl_down_sync(0xffffffffu, a2, off);
            }
            if (lane == 0) {
                g_y1[row] = a0; g_y2[row] = a1; g_y3[row] = a2;
                unsigned key = f2key(a0);
                g_key[row] = key;
                atomicAdd(&g_hist[0][key >> 16], 1u);   // fused round-0 hist
                atomicAdd(&g_hist8[0][key >> 24], 1u);
            }
        }
    }
    unsigned ph = 0;
    gbar(++ph);

    // ---------------- selection rounds (2 barriers each) ----------------
    for (int r = 0; r < 3; r++) {
        const int need = (r == 0) ? 50000 : ((r == 1) ? 25000 : 12500);
        unsigned* hist = g_hist[r];

        // C2: two-level scan in EVERY block (512 bin reads total)
        {
            unsigned own = 0;
            if (tid < 256) {
                own = __ldcg(&g_hist8[r][255 - tid]);
                s_scan[tid] = own;
            }
            __syncthreads();
#pragma unroll
            for (int off = 1; off < 256; off <<= 1) {
                unsigned v = (tid >= off && tid < 256) ? s_scan[tid - off] : 0u;
                __syncthreads();
                if (tid < 256) s_scan[tid] += v;
                __syncthreads();
            }
            if (tid < 256) {
                unsigned incl = s_scan[tid], excl = incl - own;
                if ((int)excl < need && need <= (int)incl) {
                    s_cb = 255 - tid;
                    s_nr = need - (int)excl;
                }
            }
            __syncthreads();
            const int cb = s_cb, nr = s_nr;
            unsigned own2 = 0;
            if (tid < 256) {
                own2 = __ldcg(&hist[cb * 256 + 255 - tid]);
                s_scan[tid] = own2;
            }
            __syncthreads();
#pragma unroll
            for (int off = 1; off < 256; off <<= 1) {
                unsigned v = (tid >= off && tid < 256) ? s_scan[tid - off] : 0u;
                __syncthreads();
                if (tid < 256) s_scan[tid] += v;
                __syncthreads();
            }
            if (tid < 256) {
                unsigned incl = s_scan[tid], excl = incl - own2;
                if ((int)excl < nr && nr <= (int)incl) {
                    s_Bsel = (unsigned)(cb * 256 + 255 - tid);
                    s_needB = nr - (int)excl;
                }
            }
            __syncthreads();
        }

        // C3: classify + next-round hists + append boundary candidates
        {
            const unsigned Bv = s_Bsel;
            for (int i = gtid; i < NROWS; i += GSTRIDE) {
                unsigned key = __ldcg(&g_key[i]);
                if (key) {
                    unsigned b = key >> 16;
                    if (b > Bv) {
                        unsigned nk = upd(r, i, true, i1, i2, i3);
                        if (r < 2) {
                            atomicAdd(&g_hist[r + 1][nk >> 16], 1u);
                            atomicAdd(&g_hist8[r + 1][nk >> 24], 1u);
                        }
                    } else if (b == Bv) {
                        int ci = atomicAdd(&g_ncand3[r], 1);
                        g_candk[ci] = key; g_candr[ci] = i;
                    } else {
                        upd(r, i, false, i1, i2, i3);
                    }
                } else {
                    upd(r, i, false, i1, i2, i3);   // writes coef=0 when r==2
                }
            }
        }
        gbar(++ph);

        // C4 (all blocks): rank boundary candidates, strided ownership;
        //                  also re-zero hist[r]/hist8[r] (replay invariant)
        {
            for (int i = gtid; i < 65536; i += GSTRIDE) hist[i] = 0u;
            if (bid == 0 && tid < 256) g_hist8[r][tid] = 0u;
            int m  = __ldcg(&g_ncand3[r]);
            int nB = s_needB;
            int mc = (m < SCAP) ? m : SCAP;
            for (int j = tid; j < mc; j += NT) {
                s_ck[j] = __ldcg(&g_candk[j]);
                s_cr[j] = __ldcg(&g_candr[j]);
            }
            __syncthreads();
            for (int ci = gtid; ci < m; ci += GSTRIDE) {
                unsigned mk = (ci < mc) ? s_ck[ci] : __ldcg(&g_candk[ci]);
                int      mr = (ci < mc) ? s_cr[ci] : __ldcg(&g_candr[ci]);
                int cnt = 0;
                for (int j = 0; j < mc; j++) {
                    unsigned kj = s_ck[j]; int rj = s_cr[j];
                    cnt += (kj > mk || (kj == mk && rj < mr)) ? 1 : 0;
                }
                for (int j = mc; j < m; j++) {
                    unsigned kj = __ldcg(&g_candk[j]); int rj = __ldcg(&g_candr[j]);
                    cnt += (kj > mk || (kj == mk && rj < mr)) ? 1 : 0;
                }
                bool sel = (cnt < nB);
                unsigned nk = upd(r, mr, sel, i1, i2, i3);
                if (r < 2 && sel) {
                    atomicAdd(&g_hist[r + 1][nk >> 16], 1u);
                    atomicAdd(&g_hist8[r + 1][nk >> 24], 1u);
                }
            }
        }
        gbar(++ph);
    }

    // ---------------- phase D: weighted gather, single pass ----------------
    {
        const int e = lane - 8;
        const bool haveE = (e >= 0 && e < 3);
        const int ecol = haveE ? ((e < p) ? e : p + 1440 + (e - p)) : 0;
        const int m11 = 352 + lane;
        const bool l8 = (lane < 8);
        float* fp = &g_fpart[gw][0];
        float4 acc[12];
#pragma unroll
        for (int kk = 0; kk < 12; kk++) acc[kk] = make_float4(0.f, 0.f, 0.f, 0.f);
        float accE = 0.f;
        for (int jj = wp; jj < JPP; jj += WPP) {
            int row = p + 4 * jj;
            float c = __ldcg(&g_coef[row]);
            if (c == 0.0f) continue;
            const float4* px = (const float4*)(x + (size_t)row * DIMS + p);
#pragma unroll
            for (int k = 0; k < 11; k++) {
                float4 v = __ldg(px + lane + 32 * k);
                acc[k].x += c * v.x; acc[k].y += c * v.y;
                acc[k].z += c * v.z; acc[k].w += c * v.w;
            }
            if (l8) {
                float4 v = __ldg(px + m11);
                acc[11].x += c * v.x; acc[11].y += c * v.y;
                acc[11].z += c * v.z; acc[11].w += c * v.w;
            }
            if (haveE) accE += c * __ldg(x + (size_t)row * DIMS + ecol);
        }
#pragma unroll
        for (int k = 0; k < 12; k++) {
            if (k < 11 || l8) {
                int m = (k < 11) ? (lane + 32 * k) : m11;
                int cb = p + 4 * m;
                fp[cb] = acc[k].x; fp[cb + 1] = acc[k].y;
                fp[cb + 2] = acc[k].z; fp[cb + 3] = acc[k].w;
            }
        }
        if (haveE) fp[ecol] = accE;
    }
    gbar(++ph);

    // ---------------- E1: reduce 2368 partials -> 16 ----------------
    if (gw < 736) {
        int q = gw & 15, cg = gw >> 4;
        int col = cg * 32 + lane;
        if (col < DIMS) {
            float s = 0.f;
            int j0 = q * (TOTW / 16);
#pragma unroll 8
            for (int j = j0; j < j0 + (TOTW / 16); j++) s += __ldcg(&g_fpart[j][col]);
            g_epart[q][col] = s;
        }
    }
    gbar(++ph);

    // ---------------- E2: 16 -> out ----------------
    if (gw < 46) {
        int col = gw * 32 + lane;
        if (col < DIMS) {
            float s = 0.f;
#pragma unroll
            for (int q = 0; q < 16; q++) s += __ldcg(&g_epart[q][col]);
            out[col] = s;
        }
    }

    // ---- final arrive-only barrier; block 0 resets counter for next replay ----
    __syncthreads();
    if (tid == 0) {
        __threadfence();
        const unsigned tgt = (ph + 1) * NB;
        atomicAdd(&g_bar, 1u);
        if (bid == 0) {
            while (atomicAdd(&g_bar, 0u) < tgt) __nanosleep(128);
            atomicExch(&g_bar, 0u);
            __threadfence();
        }
    }
}

// ---------------- launch ----------------
extern "C" void kernel_launch(void* const* d_in, const int* in_sizes, int n_in,
                              void* d_out, int out_size) {
    const float* x  = (const float*)d_in[0];
    // d_in[1] edge_index, d_in[2] edge_attr: dead inputs
    const float* w1 = (const float*)d_in[3];
    const float* w2 = (const float*)d_in[4];
    const float* w3 = (const float*)d_in[5];
    float* out = (float*)d_out;

    cudaFuncSetAttribute(k_persist, cudaFuncAttributeMaxDynamicSharedMemorySize,
                         DSMEM);
    k_persist<<<NB, NT, DSMEM>>>(x, w1, w2, w3, out);
}

// round 14
// speedup vs baseline: 1.1370x; 1.0101x over previous
#include <cuda_runtime.h>
#include <math.h>
#include <stdint.h>

#define NROWS 100000
#define DIMS  1443
#define NB    148
#define NT    512
#define NWARP 16
#define GSTRIDE (NB*NT)
#define WPP   (37*NWARP)        // 592 warps per alignment phase
#define JROWS 25000             // rows per phase: row = p + 4*jj
#define SCAP  1024
#define RSTAGE 2
#define ROWB  5760              // 1440 floats (16B-aligned slice of a row)
#define WPACK_BYTES (3*360*16)              // 17280
#define ROWS_BYTES (NWARP*RSTAGE*ROWB)      // 184320
#define DSMEM (WPACK_BYTES + ROWS_BYTES)    // 201600
#define ACCW  1444                          // padded gather-stage row

// ---------------- device scratch (allocation-free) ----------------
__device__ unsigned g_bar = 0;
__device__ float    g_y1[NROWS], g_y2[NROWS], g_y3[NROWS];
__device__ float    g_prod[NROWS];
__device__ float    g_coef[NROWS];
__device__ unsigned g_key[NROWS];
__device__ unsigned g_hist[3][65536];     // zeroed in C4 of its round (replay invariant)
__device__ unsigned g_hist8[3][256];      // coarse (key>>24), same lifecycle
__device__ unsigned g_candk[NROWS];
__device__ int      g_candr[NROWS];
__device__ int      g_ncand3[3];
__device__ float    g_fpart[NB][DIMS];    // per-BLOCK gather partials

__device__ __forceinline__ unsigned f2key(float f) {
    unsigned u = __float_as_uint(f);
    return (u & 0x80000000u) ? ~u : (u | 0x80000000u);   // never 0 for finite f
}
__device__ __forceinline__ uint32_t s2u(const void* p) {
    uint32_t a;
    asm("{ .reg .u64 t; cvta.to.shared.u64 t, %1; cvt.u32.u64 %0, t; }"
        : "=r"(a) : "l"(p));
    return a;
}
__device__ __forceinline__ void mb_init(uint32_t m, uint32_t c) {
    asm volatile("mbarrier.init.shared.b64 [%0], %1;" :: "r"(m), "r"(c) : "memory");
}
__device__ __forceinline__ void mb_extx(uint32_t m, uint32_t b) {
    asm volatile("mbarrier.arrive.expect_tx.shared.b64 _, [%0], %1;"
                 :: "r"(m), "r"(b) : "memory");
}
__device__ __forceinline__ void bulk_g2s(uint32_t dst, const void* src,
                                         uint32_t bytes, uint32_t m) {
    asm volatile("cp.async.bulk.shared::cta.global.mbarrier::complete_tx::bytes "
                 "[%0], [%1], %2, [%3];"
                 :: "r"(dst), "l"(src), "r"(bytes), "r"(m) : "memory");
}
__device__ __forceinline__ void mb_wait(uint32_t m, uint32_t par) {
    uint32_t done;
    asm volatile(
        "{ .reg .pred p; mbarrier.try_wait.parity.acquire.cta.shared::cta.b64 "
        "p, [%1], %2; selp.b32 %0,1,0,p; }"
        : "=r"(done) : "r"(m), "r"(par) : "memory");
    while (!done) {
        asm volatile(
            "{ .reg .pred p; mbarrier.try_wait.parity.acquire.cta.shared::cta.b64 "
            "p, [%1], %2, 0x989680; selp.b32 %0,1,0,p; }"
            : "=r"(done) : "r"(m), "r"(par) : "memory");
    }
}
__device__ __forceinline__ void fence_async() {
    asm volatile("fence.proxy.async.shared::cta;" ::: "memory");
}

// grid barrier: arrival via atomicAdd; spin via plain volatile L2 load
// (atomic polls serialize on the LTS atomic ALU; loads broadcast).
// fence(release) before add + fence(acquire) after observing target.
__device__ __forceinline__ void gbar(unsigned ph) {
    __syncthreads();
    if (threadIdx.x == 0) {
        __threadfence();
        atomicAdd(&g_bar, 1u);
        const unsigned tgt = ph * NB;
        while (*(volatile unsigned*)&g_bar < tgt) __nanosleep(64);
        __threadfence();
    }
    __syncthreads();
}

// per-row round update; returns new key (0 if dropped / r==2)
__device__ __forceinline__ unsigned upd(int r, int i, bool sel,
                                        float i1, float i2, float i3) {
    if (r == 0) {
        if (sel) {
            float s = tanhf(__ldcg(&g_y1[i]) * i1);
            g_prod[i] = s;
            unsigned nk = f2key(s * __ldcg(&g_y2[i]));
            g_key[i] = nk;
            return nk;
        }
        g_key[i] = 0u; return 0u;
    } else if (r == 1) {
        if (sel) {
            float p = __ldcg(&g_prod[i]);
            float s = tanhf(p * __ldcg(&g_y2[i]) * i2);
            p *= s;
            g_prod[i] = p;
            unsigned nk = f2key(p * __ldcg(&g_y3[i]));
            g_key[i] = nk;
            return nk;
        }
        g_key[i] = 0u; return 0u;
    } else {
        float cf = 0.f;
        if (sel) {
            float p = __ldcg(&g_prod[i]);
            float s = tanhf(p * __ldcg(&g_y3[i]) * i3);
            cf = p * s * (1.0f / 12500.0f);
        }
        g_coef[i] = cf;
        return 0u;
    }
}

extern __shared__ float4 dsm4[];   // [w-pack 1080 f4][row buffers 16*2*360 f4]

__global__ void __launch_bounds__(NT, 1) k_persist(
    const float* __restrict__ x,
    const float* __restrict__ w1, const float* __restrict__ w2,
    const float* __restrict__ w3, float* __restrict__ out)
{
    const int tid  = threadIdx.x, bid = blockIdx.x;
    const int lane = tid & 31,    wid = tid >> 5;
    const int gw   = bid * NWARP + wid;
    const int gtid = bid * NT + tid;
    const int p    = bid & 3;                  // alignment phase of this block
    const int wp   = (bid >> 2) * NWARP + wid; // warp id within phase [0,592)

    float4* s_wp = dsm4;                       // [3][360]
    float4* s_rw = dsm4 + 3 * 360;             // [16][RSTAGE][360] (GEMV) / gather stage

    __shared__ float    s_n[3][NWARP];
    __shared__ float    s_inv[3];
    __shared__ unsigned s_scan[256];
    __shared__ unsigned s_ck[SCAP];
    __shared__ int      s_cr[SCAP];
    __shared__ unsigned s_Bsel;
    __shared__ int      s_needB;
    __shared__ int      s_cb, s_nr;
    __shared__ __align__(8) uint64_t s_mb[NWARP][RSTAGE];

    // ---- w norms (block-local, redundant across blocks) ----
    {
        float a0 = 0.f, a1 = 0.f, a2 = 0.f;
        for (int i = tid; i < DIMS; i += NT) {
            float v1 = __ldg(w1 + i), v2 = __ldg(w2 + i), v3 = __ldg(w3 + i);
            a0 += v1 * v1; a1 += v2 * v2; a2 += v3 * v3;
        }
#pragma unroll
        for (int off = 16; off > 0; off >>= 1) {
            a0 += __shfl_down_sync(0xffffffffu, a0, off);
            a1 += __shfl_down_sync(0xffffffffu, a1, off);
            a2 += __shfl_down_sync(0xffffffffu, a2, off);
        }
        if (lane == 0) { s_n[0][wid] = a0; s_n[1][wid] = a1; s_n[2][wid] = a2; }
    }
    // ---- fill phase-local w-pack; init mbarriers; zero counters ----
    for (int idx = tid; idx < 3 * 360; idx += NT) {
        int v = idx / 360, m = idx % 360;
        const float* w = (v == 0) ? w1 : ((v == 1) ? w2 : w3);
        int col = p + 4 * m;
        s_wp[idx] = make_float4(__ldg(w + col), __ldg(w + col + 1),
                                __ldg(w + col + 2), __ldg(w + col + 3));
    }
    if (tid < NWARP * RSTAGE) {
        mb_init(s2u(&s_mb[tid >> 1][tid & 1]), 1);
        fence_async();
    }
    if (bid == 0 && tid < 3) g_ncand3[tid] = 0;
    __syncthreads();
    if (tid < 3) {
        float s = 0.f;
        for (int w = 0; w < NWARP; w++) s += s_n[tid][w];
        s_inv[tid] = 1.0f / sqrtf(s);
    }
    __syncthreads();
    const float i1 = s_inv[0], i2 = s_inv[1], i3 = s_inv[2];

    // ---------------- phase B: GEMV, per-warp bulk-copy ring (TMA path) ----------------
    {
        const float4* wpa = s_wp;
        const float4* wpb = s_wp + 360;
        const float4* wpc = s_wp + 720;
        const int e = lane - 8;
        const bool haveE = (e >= 0 && e < 3);
        int ecol = 0; float we1 = 0.f, we2 = 0.f, we3 = 0.f;
        if (haveE) {
            ecol = (e < p) ? e : p + 1440 + (e - p);
            we1 = __ldg(w1 + ecol); we2 = __ldg(w2 + ecol); we3 = __ldg(w3 + ecol);
        }
        const uint32_t rwBase = s2u(s_rw);
        const uint32_t mbA[2] = { s2u(&s_mb[wid][0]), s2u(&s_mb[wid][1]) };

        auto issueRow = [&](int jj, int slot) {
            if (jj < JROWS && lane == 0) {
                int row = p + 4 * jj;
                const float* src = x + (size_t)row * DIMS + p;   // 16B aligned
                uint32_t dst = rwBase + (uint32_t)(wid * RSTAGE + slot) * ROWB;
                mb_extx(mbA[slot], ROWB);
                bulk_g2s(dst, src, ROWB, mbA[slot]);
            }
        };
        issueRow(wp, 0);
        issueRow(wp + WPP, 1);

        int phs0 = 0, phs1 = 0, t = 0;
        for (int jj = wp; jj < JROWS; jj += WPP, ++t) {
            const int slot = t & 1;
            const int row = p + 4 * jj;
            float xe = haveE ? __ldcg(x + (size_t)row * DIMS + ecol) : 0.f;
            if (slot == 0) { mb_wait(mbA[0], phs0); phs0 ^= 1; }
            else           { mb_wait(mbA[1], phs1); phs1 ^= 1; }
            const float4* rb = s_rw + (wid * RSTAGE + slot) * 360;
            float a0 = 0.f, a1 = 0.f, a2 = 0.f;
#pragma unroll
            for (int k = 0; k < 11; k++) {
                int m = lane + 32 * k;
                float4 v = rb[m];
                float4 wa = wpa[m], wbv = wpb[m], wc = wpc[m];
                a0 += v.x*wa.x  + v.y*wa.y  + v.z*wa.z  + v.w*wa.w;
                a1 += v.x*wbv.x + v.y*wbv.y + v.z*wbv.z + v.w*wbv.w;
                a2 += v.x*wc.x  + v.y*wc.y  + v.z*wc.z  + v.w*wc.w;
            }
            if (lane < 8) {
                int m = 352 + lane;
                float4 v = rb[m];
                float4 wa = wpa[m], wbv = wpb[m], wc = wpc[m];
                a0 += v.x*wa.x  + v.y*wa.y  + v.z*wa.z  + v.w*wa.w;
                a1 += v.x*wbv.x + v.y*wbv.y + v.z*wbv.z + v.w*wbv.w;
                a2 += v.x*wc.x  + v.y*wc.y  + v.z*wc.z  + v.w*wc.w;
            }
            if (haveE) { a0 += xe * we1; a1 += xe * we2; a2 += xe * we3; }
            fence_async();                // order smem reads before async reuse
            __syncwarp();                 // all lanes' fences precede lane0's re-issue
            issueRow(jj + 2 * WPP, slot); // refill slot
#pragma unroll
            for (int off = 16; off > 0; off >>= 1) {
                a0 += __shfl_down_sync(0xffffffffu, a0, off);
                a1 += __shfl_down_sync(0xffffffffu, a1, off);
                a2 += __shfl_down_sync(0xffffffffu, a2, off);
            }
            if (lane == 0) {
                g_y1[row] = a0; g_y2[row] = a1; g_y3[row] = a2;
                unsigned key = f2key(a0);
                g_key[row] = key;
                atomicAdd(&g_hist[0][key >> 16], 1u);   // fused round-0 hist
                atomicAdd(&g_hist8[0][key >> 24], 1u);
            }
        }
    }
    unsigned ph = 0;
    gbar(++ph);

    // ---------------- selection rounds (2 barriers each) ----------------
    for (int r = 0; r < 3; r++) {
        const int need = (r == 0) ? 50000 : ((r == 1) ? 25000 : 12500);
        unsigned* hist = g_hist[r];

        // C2: two-level scan in EVERY block (512 bin reads total)
        {
            unsigned own = 0;
            if (tid < 256) {
                own = __ldcg(&g_hist8[r][255 - tid]);
                s_scan[tid] = own;
            }
            __syncthreads();
#pragma unroll
            for (int off = 1; off < 256; off <<= 1) {
                unsigned v = (tid >= off && tid < 256) ? s_scan[tid - off] : 0u;
                __syncthreads();
                if (tid < 256) s_scan[tid] += v;
                __syncthreads();
            }
            if (tid < 256) {
                unsigned incl = s_scan[tid], excl = incl - own;
                if ((int)excl < need && need <= (int)incl) {
                    s_cb = 255 - tid;
                    s_nr = need - (int)excl;
                }
            }
            __syncthreads();
            const int cb = s_cb, nr = s_nr;
            unsigned own2 = 0;
            if (tid < 256) {
                own2 = __ldcg(&hist[cb * 256 + 255 - tid]);
                s_scan[tid] = own2;
            }
            __syncthreads();
#pragma unroll
            for (int off = 1; off < 256; off <<= 1) {
                unsigned v = (tid >= off && tid < 256) ? s_scan[tid - off] : 0u;
                __syncthreads();
                if (tid < 256) s_scan[tid] += v;
                __syncthreads();
            }
            if (tid < 256) {
                unsigned incl = s_scan[tid], excl = incl - own2;
                if ((int)excl < nr && nr <= (int)incl) {
                    s_Bsel = (unsigned)(cb * 256 + 255 - tid);
                    s_needB = nr - (int)excl;
                }
            }
            __syncthreads();
        }

        // C3: classify + next-round hists + append boundary candidates
        {
            const unsigned Bv = s_Bsel;
            for (int i = gtid; i < NROWS; i += GSTRIDE) {
                unsigned key = __ldcg(&g_key[i]);
                if (key) {
                    unsigned b = key >> 16;
                    if (b > Bv) {
                        unsigned nk = upd(r, i, true, i1, i2, i3);
                        if (r < 2) {
                            atomicAdd(&g_hist[r + 1][nk >> 16], 1u);
                            atomicAdd(&g_hist8[r + 1][nk >> 24], 1u);
                        }
                    } else if (b == Bv) {
                        int ci = atomicAdd(&g_ncand3[r], 1);
                        g_candk[ci] = key; g_candr[ci] = i;
                    } else {
                        upd(r, i, false, i1, i2, i3);
                    }
                } else {
                    upd(r, i, false, i1, i2, i3);   // writes coef=0 when r==2
                }
            }
        }
        gbar(++ph);

        // C4 (all blocks): rank boundary candidates, strided ownership;
        //                  also re-zero hist[r]/hist8[r] (replay invariant)
        {
            for (int i = gtid; i < 65536; i += GSTRIDE) hist[i] = 0u;
            if (bid == 0 && tid < 256) g_hist8[r][tid] = 0u;
            int m  = __ldcg(&g_ncand3[r]);
            int nB = s_needB;
            int mc = (m < SCAP) ? m : SCAP;
            for (int j = tid; j < mc; j += NT) {
                s_ck[j] = __ldcg(&g_candk[j]);
                s_cr[j] = __ldcg(&g_candr[j]);
            }
            __syncthreads();
            for (int ci = gtid; ci < m; ci += GSTRIDE) {
                unsigned mk = (ci < mc) ? s_ck[ci] : __ldcg(&g_candk[ci]);
                int      mr = (ci < mc) ? s_cr[ci] : __ldcg(&g_candr[ci]);
                int cnt = 0;
                for (int j = 0; j < mc; j++) {
                    unsigned kj = s_ck[j]; int rj = s_cr[j];
                    cnt += (kj > mk || (kj == mk && rj < mr)) ? 1 : 0;
                }
                for (int j = mc; j < m; j++) {
                    unsigned kj = __ldcg(&g_candk[j]); int rj = __ldcg(&g_candr[j]);
                    cnt += (kj > mk || (kj == mk && rj < mr)) ? 1 : 0;
                }
                bool sel = (cnt < nB);
                unsigned nk = upd(r, mr, sel, i1, i2, i3);
                if (r < 2 && sel) {
                    atomicAdd(&g_hist[r + 1][nk >> 16], 1u);
                    atomicAdd(&g_hist8[r + 1][nk >> 24], 1u);
                }
            }
        }
        gbar(++ph);
    }

    // ---------------- phase D: gather + block-level smem reduction ----------------
    {
        const int e = lane - 8;
        const bool haveE = (e >= 0 && e < 3);
        const int ecol = haveE ? ((e < p) ? e : p + 1440 + (e - p)) : 0;
        const int m11 = 352 + lane;
        const bool l8 = (lane < 8);
        float4 acc[12];
#pragma unroll
        for (int kk = 0; kk < 12; kk++) acc[kk] = make_float4(0.f, 0.f, 0.f, 0.f);
        float accE = 0.f;
        for (int jj = wp; jj < JROWS; jj += WPP) {
            int row = p + 4 * jj;
            float c = __ldcg(&g_coef[row]);
            if (c == 0.0f) continue;
            const float4* px = (const float4*)(x + (size_t)row * DIMS + p);
#pragma unroll
            for (int k = 0; k < 11; k++) {
                float4 v = __ldg(px + lane + 32 * k);
                acc[k].x += c * v.x; acc[k].y += c * v.y;
                acc[k].z += c * v.z; acc[k].w += c * v.w;
            }
            if (l8) {
                float4 v = __ldg(px + m11);
                acc[11].x += c * v.x; acc[11].y += c * v.y;
                acc[11].z += c * v.z; acc[11].w += c * v.w;
            }
            if (haveE) accE += c * __ldg(x + (size_t)row * DIMS + ecol);
        }
        // stage per-warp partials in smem (row-buffer region is free now)
        float* sa = (float*)s_rw + wid * ACCW;
#pragma unroll
        for (int k = 0; k < 12; k++) {
            if (k < 11 || l8) {
                int m = (k < 11) ? (lane + 32 * k) : m11;
                int cb = p + 4 * m;
                sa[cb] = acc[k].x; sa[cb + 1] = acc[k].y;
                sa[cb + 2] = acc[k].z; sa[cb + 3] = acc[k].w;
            }
        }
        if (haveE) sa[ecol] = accE;
        __syncthreads();
        // block reduce: each thread owns cols tid, tid+512, tid+1024
        const float* base = (const float*)s_rw;
        for (int col = tid; col < DIMS; col += NT) {
            float s = 0.f;
#pragma unroll
            for (int w = 0; w < NWARP; w++) s += base[w * ACCW + col];
            g_fpart[bid][col] = s;
        }
    }
    gbar(++ph);

    // ---------------- E: reduce 148 block partials -> out (one phase) ----------------
    if (gw < 46) {
        int col = gw * 32 + lane;
        if (col < DIMS) {
            float s = 0.f;
#pragma unroll 8
            for (int j = 0; j < NB; j++) s += __ldcg(&g_fpart[j][col]);
            out[col] = s;
        }
    }

    // ---- final arrive-only barrier; block 0 resets counter for next replay ----
    __syncthreads();
    if (tid == 0) {
        __threadfence();
        const unsigned tgt = (ph + 1) * NB;
        atomicAdd(&g_bar, 1u);
        if (bid == 0) {
            while (*(volatile unsigned*)&g_bar < tgt) __nanosleep(64);
            atomicExch(&g_bar, 0u);
            __threadfence();
        }
    }
}

// ---------------- launch ----------------
extern "C" void kernel_launch(void* const* d_in, const int* in_sizes, int n_in,
                              void* d_out, int out_size) {
    const float* x  = (const float*)d_in[0];
    // d_in[1] edge_index, d_in[2] edge_attr: dead inputs
    const float* w1 = (const float*)d_in[3];
    const float* w2 = (const float*)d_in[4];
    const float* w3 = (const float*)d_in[5];
    float* out = (float*)d_out;

    cudaFuncSetAttribute(k_persist, cudaFuncAttributeMaxDynamicSharedMemorySize,
                         DSMEM);
    k_persist<<<NB, NT, DSMEM>>>(x, w1, w2, w3, out);
}